// round 2
// baseline (speedup 1.0000x reference)
#include <cuda_runtime.h>
#include <math.h>

#define MAXN 100000
#define DM 32
#define RK 16

// Scratch (no allocations allowed)
__device__ int    g_deg[MAXN];
__device__ float  g_dinv[MAXN];
__device__ double g_acc[4];          // 0: sum(z_mean^2), 1: sum w*<m_r,m_c>, 2: sum w*<s_r,s_c>, 3: sum selfloop w
__device__ double g_gram[RK * RK];   // z_std^T z_std

// ---------------------------------------------------------------------------
__global__ void k_zero(int N) {
    int i = blockIdx.x * blockDim.x + threadIdx.x;
    if (i < N) g_deg[i] = 0;
    if (i < 4) g_acc[i] = 0.0;
    if (i < RK * RK) g_gram[i] = 0.0;
}

// degree histogram from row indices (edge_index is int32: JAX x64 disabled)
__global__ void k_deg(const int* __restrict__ ei, int E) {
    int e = blockIdx.x * blockDim.x + threadIdx.x;
    if (e < E) atomicAdd(&g_deg[ei[e]], 1);
}

__global__ void k_dinv(int N) {
    int i = blockIdx.x * blockDim.x + threadIdx.x;
    if (i < N) {
        int d = g_deg[i];
        g_dinv[i] = (d > 0) ? rsqrtf((float)d) : 0.0f;
    }
}

// flat sum of squares of z_mean (vectorized)
__global__ void k_sumsq(const float4* __restrict__ x, int n4) {
    float acc = 0.0f;
    for (int i = blockIdx.x * blockDim.x + threadIdx.x; i < n4;
         i += gridDim.x * blockDim.x) {
        float4 v = x[i];
        acc += v.x * v.x + v.y * v.y + v.z * v.z + v.w * v.w;
    }
    for (int o = 16; o; o >>= 1) acc += __shfl_xor_sync(0xffffffffu, acc, o);
    __shared__ float sh[8];
    int w = threadIdx.x >> 5, l = threadIdx.x & 31;
    if (l == 0) sh[w] = acc;
    __syncthreads();
    if (threadIdx.x == 0) {
        float s = 0.0f;
        int nw = blockDim.x >> 5;
        for (int i = 0; i < nw; i++) s += sh[i];
        atomicAdd(&g_acc[0], (double)s);
    }
}

// Gram = z_std^T z_std via 256-row shared tiles; 256 threads, thread j -> entry (j>>4, j&15)
__global__ void k_gram(const float* __restrict__ zs, int N) {
    __shared__ float sh[256 * RK];
    int row0 = blockIdx.x * 256;
    for (int t = threadIdx.x; t < 256 * RK / 4; t += blockDim.x) {
        int row = row0 + (t >> 2);   // 4 float4 per row
        float4 v = make_float4(0.f, 0.f, 0.f, 0.f);
        if (row < N) v = ((const float4*)zs)[(size_t)row0 * 4 + t];
        ((float4*)sh)[t] = v;
    }
    __syncthreads();
    int a = threadIdx.x >> 4, b = threadIdx.x & 15;
    float acc = 0.0f;
#pragma unroll 8
    for (int i = 0; i < 256; i++) acc += sh[i * RK + a] * sh[i * RK + b];
    atomicAdd(&g_gram[threadIdx.x], (double)acc);
}

// dominant kernel: per-edge gather + dots. 8 threads cooperate per edge.
__global__ void __launch_bounds__(256) k_edges(
    const float* __restrict__ zm, const float* __restrict__ zs,
    const int* __restrict__ ei, int E) {
    int tid = blockIdx.x * blockDim.x + threadIdx.x;
    int sub = threadIdx.x & 7;
    int gid = tid >> 3;
    int gstride = (gridDim.x * blockDim.x) >> 3;

    float am = 0.0f, as = 0.0f, aself = 0.0f;

    int iters = (E + gstride - 1) / gstride;  // uniform trip count -> safe shuffles
    for (int it = 0; it < iters; it++) {
        int e = gid + it * gstride;
        bool act = (e < E);
        int es = act ? e : 0;
        int r = ei[es];
        int c = ei[(size_t)E + es];

        // z_mean rows: 8 lanes x float4 = 128B coalesced per row
        const float4* mr = (const float4*)(zm + (size_t)r * DM);
        const float4* mc = (const float4*)(zm + (size_t)c * DM);
        float4 x = mr[sub], y = mc[sub];
        float dm = x.x * y.x + x.y * y.y + x.z * y.z + x.w * y.w;

        // z_std rows: 8 lanes x float2 = 64B
        const float2* sr = (const float2*)(zs + (size_t)r * RK);
        const float2* sc = (const float2*)(zs + (size_t)c * RK);
        float2 u = sr[sub], v = sc[sub];
        float ds = u.x * v.x + u.y * v.y;

        // reduce over the 8-lane group
        dm += __shfl_xor_sync(0xffffffffu, dm, 1);
        dm += __shfl_xor_sync(0xffffffffu, dm, 2);
        dm += __shfl_xor_sync(0xffffffffu, dm, 4);
        ds += __shfl_xor_sync(0xffffffffu, ds, 1);
        ds += __shfl_xor_sync(0xffffffffu, ds, 2);
        ds += __shfl_xor_sync(0xffffffffu, ds, 4);

        if (sub == 0 && act) {
            float w = g_dinv[r] * g_dinv[c];
            am += w * dm;
            as += w * ds;
            if (r == c) aself += w;
        }
    }

    // block reduce the 3 accumulators (non-leader lanes hold 0)
    for (int o = 16; o; o >>= 1) {
        am += __shfl_xor_sync(0xffffffffu, am, o);
        as += __shfl_xor_sync(0xffffffffu, as, o);
        aself += __shfl_xor_sync(0xffffffffu, aself, o);
    }
    __shared__ float s0[8], s1[8], s2[8];
    int w = threadIdx.x >> 5, l = threadIdx.x & 31;
    if (l == 0) { s0[w] = am; s1[w] = as; s2[w] = aself; }
    __syncthreads();
    if (threadIdx.x == 0) {
        float A = 0.f, B = 0.f, C = 0.f;
        int nw = blockDim.x >> 5;
        for (int i = 0; i < nw; i++) { A += s0[i]; B += s1[i]; C += s2[i]; }
        atomicAdd(&g_acc[1], (double)A);
        atomicAdd(&g_acc[2], (double)B);
        atomicAdd(&g_acc[3], (double)C);
    }
}

// finalize: logdet(I + Gram) via Cholesky in double, combine, write scalar
__global__ void k_final(float* out, int N) {
    if (threadIdx.x == 0 && blockIdx.x == 0) {
        double M[RK][RK];
        double tr = 0.0;
        for (int i = 0; i < RK; i++) {
            for (int j = 0; j < RK; j++)
                M[i][j] = g_gram[i * RK + j] + (i == j ? 1.0 : 0.0);
            tr += g_gram[i * RK + i];  // sum(z_std^2) = trace(Gram)
        }
        double logdet = 0.0;
        for (int k = 0; k < RK; k++) {
            double d = M[k][k];
            for (int j = 0; j < k; j++) d -= M[k][j] * M[k][j];
            double lkk = sqrt(d);
            logdet += log(lkk);
            M[k][k] = lkk;
            for (int i = k + 1; i < RK; i++) {
                double s = M[i][k];
                for (int j = 0; j < k; j++) s -= M[i][j] * M[k][j];
                M[i][k] = s / lkk;
            }
        }
        logdet *= 2.0;

        double trace_L = (double)N - g_acc[3];
        double l2 = (tr - g_acc[2]) + trace_L;       // beta = 1
        double l3 = g_acc[0] - g_acc[1];
        double res = (l3 / (double)DM + l2 - logdet) / (2.0 * (double)N);
        out[0] = (float)res;
    }
}

// ---------------------------------------------------------------------------
extern "C" void kernel_launch(void* const* d_in, const int* in_sizes, int n_in,
                              void* d_out, int out_size) {
    const float* zm = (const float*)d_in[0];
    const float* zs = (const float*)d_in[1];
    const int*   ei = (const int*)d_in[2];

    int N = in_sizes[0] / DM;
    int E = in_sizes[2] / 2;

    int nb = (N + 255) / 256;
    k_zero<<<nb, 256>>>(N);
    k_deg<<<(E + 255) / 256, 256>>>(ei, E);
    k_dinv<<<nb, 256>>>(N);
    k_sumsq<<<1024, 256>>>((const float4*)zm, N * DM / 4);
    k_gram<<<nb, 256>>>(zs, N);
    k_edges<<<2368, 256>>>(zm, zs, ei, E);
    k_final<<<1, 32>>>((float*)d_out, N);
}

// round 3
// speedup vs baseline: 1.2282x; 1.2282x over previous
#include <cuda_runtime.h>
#include <cuda_fp16.h>
#include <math.h>

#define MAXN 100000
#define DM 32
#define RK 16
#define PKW 48   // packed row width in halves (32 mean + 16 std) = 96 bytes

// Scratch (no allocations allowed)
__device__ int    g_deg[MAXN];
__device__ float  g_dinv[MAXN];
__device__ double g_acc[3];          // 0: sum(z_mean^2), 1: D = sum_e <q_r,q_c>, 2: selfloop w sum
__device__ double g_gram[RK * RK];   // z_std^T z_std
__device__ __align__(16) __half g_pack[MAXN * PKW];  // 9.6 MB packed scaled rows

// ---------------------------------------------------------------------------
__global__ void k_zero(int N) {
    int i = blockIdx.x * blockDim.x + threadIdx.x;
    if (i < N) g_deg[i] = 0;
    if (i < 3) g_acc[i] = 0.0;
    if (i < RK * RK) g_gram[i] = 0.0;
}

// degree histogram from row indices (edge_index is int32)
__global__ void k_deg(const int* __restrict__ ei, int E) {
    int e = blockIdx.x * blockDim.x + threadIdx.x;
    if (e < E) atomicAdd(&g_deg[ei[e]], 1);
}

__global__ void k_dinv(int N) {
    int i = blockIdx.x * blockDim.x + threadIdx.x;
    if (i < N) {
        int d = g_deg[i];
        g_dinv[i] = (d > 0) ? rsqrtf((float)d) : 0.0f;
    }
}

// Pack per-node scaled rows to fp16; also accumulate sum(z_mean^2).
// 8 threads per node row; 256 threads -> 32 rows/block.
__global__ void __launch_bounds__(256) k_pack(
    const float* __restrict__ zm, const float* __restrict__ zs, int N) {
    const float MS = 0.17677669529663687f;  // 1/sqrt(32)
    int sub = threadIdx.x & 7;
    int row = blockIdx.x * 32 + (threadIdx.x >> 3);

    float acc = 0.0f;
    if (row < N) {
        float di = g_dinv[row];
        float ms = di * MS;
        // mean: 8 lanes x float4 = full 32-float row
        float4 mv = ((const float4*)(zm + (size_t)row * DM))[sub];
        acc = mv.x * mv.x + mv.y * mv.y + mv.z * mv.z + mv.w * mv.w;
        __half2* po = (__half2*)(g_pack + (size_t)row * PKW + sub * 4);
        po[0] = __floats2half2_rn(mv.x * ms, mv.y * ms);
        po[1] = __floats2half2_rn(mv.z * ms, mv.w * ms);
        // std: lanes 0-3 x float4 = 16-float row
        if (sub < 4) {
            float4 sv = ((const float4*)(zs + (size_t)row * RK))[sub];
            __half2* ps = (__half2*)(g_pack + (size_t)row * PKW + 32 + sub * 4);
            ps[0] = __floats2half2_rn(sv.x * di, sv.y * di);
            ps[1] = __floats2half2_rn(sv.z * di, sv.w * di);
        }
    }
    // block reduce sumsq
    for (int o = 16; o; o >>= 1) acc += __shfl_xor_sync(0xffffffffu, acc, o);
    __shared__ float sh[8];
    int w = threadIdx.x >> 5, l = threadIdx.x & 31;
    if (l == 0) sh[w] = acc;
    __syncthreads();
    if (threadIdx.x == 0) {
        float s = 0.0f;
        for (int i = 0; i < 8; i++) s += sh[i];
        atomicAdd(&g_acc[0], (double)s);
    }
}

// Gram = z_std^T z_std via 256-row shared tiles
__global__ void k_gram(const float* __restrict__ zs, int N) {
    __shared__ float sh[256 * RK];
    int row0 = blockIdx.x * 256;
    for (int t = threadIdx.x; t < 256 * RK / 4; t += blockDim.x) {
        int row = row0 + (t >> 2);
        float4 v = make_float4(0.f, 0.f, 0.f, 0.f);
        if (row < N) v = ((const float4*)zs)[(size_t)row0 * 4 + t];
        ((float4*)sh)[t] = v;
    }
    __syncthreads();
    int a = threadIdx.x >> 4, b = threadIdx.x & 15;
    float acc = 0.0f;
#pragma unroll 8
    for (int i = 0; i < 256; i++) acc += sh[i * RK + a] * sh[i * RK + b];
    atomicAdd(&g_gram[threadIdx.x], (double)acc);
}

// Dominant kernel: per-edge fused dot of packed fp16 rows.
// 8 threads/edge (6 active for loads); NO per-edge reduction -- lanes
// accumulate partial products privately, reduced once at the end.
__global__ void __launch_bounds__(256) k_edges(const int* __restrict__ ei, int E) {
    int tid = blockIdx.x * blockDim.x + threadIdx.x;
    int sub = threadIdx.x & 7;
    int gid = tid >> 3;
    int gstride = (gridDim.x * blockDim.x) >> 3;

    float accD = 0.0f, aself = 0.0f;
    bool lanev = (sub < 6);

    int iters = (E + gstride - 1) / gstride;
#pragma unroll 2
    for (int it = 0; it < iters; it++) {
        int e = gid + it * gstride;
        bool act = (e < E);
        int es = act ? e : 0;
        int r = ei[es];
        int c = ei[(size_t)E + es];

        if (act) {
            if (lanev) {
                const uint4* pr = (const uint4*)(g_pack + (size_t)r * PKW);
                const uint4* pc = (const uint4*)(g_pack + (size_t)c * PKW);
                uint4 ua = pr[sub];
                uint4 ub = pc[sub];
                const __half2* ha = (const __half2*)&ua;
                const __half2* hb = (const __half2*)&ub;
#pragma unroll
                for (int k = 0; k < 4; k++) {
                    float2 fa = __half22float2(ha[k]);
                    float2 fb = __half22float2(hb[k]);
                    accD = fmaf(fa.x, fb.x, accD);
                    accD = fmaf(fa.y, fb.y, accD);
                }
            }
            if (sub == 0 && r == c) {
                float di = g_dinv[r];
                aself += di * di;
            }
        }
    }

    // block reduce
    for (int o = 16; o; o >>= 1) {
        accD += __shfl_xor_sync(0xffffffffu, accD, o);
        aself += __shfl_xor_sync(0xffffffffu, aself, o);
    }
    __shared__ float s0[8], s1[8];
    int w = threadIdx.x >> 5, l = threadIdx.x & 31;
    if (l == 0) { s0[w] = accD; s1[w] = aself; }
    __syncthreads();
    if (threadIdx.x == 0) {
        float A = 0.f, B = 0.f;
        for (int i = 0; i < 8; i++) { A += s0[i]; B += s1[i]; }
        atomicAdd(&g_acc[1], (double)A);
        atomicAdd(&g_acc[2], (double)B);
    }
}

// finalize: logdet(I + Gram) via double Cholesky, combine, write scalar
__global__ void k_final(float* out, int N) {
    if (threadIdx.x == 0 && blockIdx.x == 0) {
        double M[RK][RK];
        double tr = 0.0;
        for (int i = 0; i < RK; i++) {
            for (int j = 0; j < RK; j++)
                M[i][j] = g_gram[i * RK + j] + (i == j ? 1.0 : 0.0);
            tr += g_gram[i * RK + i];  // sum(z_std^2) = trace(Gram)
        }
        double logdet = 0.0;
        for (int k = 0; k < RK; k++) {
            double d = M[k][k];
            for (int j = 0; j < k; j++) d -= M[k][j] * M[k][j];
            double lkk = sqrt(d);
            logdet += log(lkk);
            M[k][k] = lkk;
            for (int i = k + 1; i < RK; i++) {
                double s = M[i][k];
                for (int j = 0; j < k; j++) s -= M[i][j] * M[k][j];
                M[i][k] = s / lkk;
            }
        }
        logdet *= 2.0;

        double trace_L = (double)N - g_acc[2];
        // loss = (sumsq_m/32 + tr + trace_L - D - logdet) / (2N)
        double res = (g_acc[0] / (double)DM + tr + trace_L - g_acc[1] - logdet)
                     / (2.0 * (double)N);
        out[0] = (float)res;
    }
}

// ---------------------------------------------------------------------------
extern "C" void kernel_launch(void* const* d_in, const int* in_sizes, int n_in,
                              void* d_out, int out_size) {
    const float* zm = (const float*)d_in[0];
    const float* zs = (const float*)d_in[1];
    const int*   ei = (const int*)d_in[2];

    int N = in_sizes[0] / DM;
    int E = in_sizes[2] / 2;

    int nb = (N + 255) / 256;
    k_zero<<<nb, 256>>>(N);
    k_deg<<<(E + 255) / 256, 256>>>(ei, E);
    k_dinv<<<nb, 256>>>(N);
    k_pack<<<(N + 31) / 32, 256>>>(zm, zs, N);
    k_gram<<<nb, 256>>>(zs, N);
    k_edges<<<1184, 256>>>(ei, E);   // 1184*256 = one full wave @2048 thr/SM
    k_final<<<1, 32>>>((float*)d_out, N);
}

// round 4
// speedup vs baseline: 1.3626x; 1.1095x over previous
#include <cuda_runtime.h>
#include <cuda_fp16.h>
#include <cuda_fp8.h>
#include <math.h>

#define MAXN 100000
#define DM 32
#define RK 16
#define PKW32 12   // packed row width in uint32: 48 B = 32 mean fp8 + 16 std fp8

// Scratch (no allocations allowed)
__device__ int    g_deg[MAXN];
__device__ float  g_dinv[MAXN];
__device__ double g_acc[3];          // 0: sum(z_mean^2), 1: D = sum_e <q_r,q_c>, 2: selfloop w sum
__device__ double g_gram[RK * RK];   // z_std^T z_std
__device__ __align__(16) unsigned g_pack[MAXN * PKW32];  // 4.8 MB fp8 rows

// ---------------------------------------------------------------------------
__global__ void k_zero(int N) {
    int i = blockIdx.x * blockDim.x + threadIdx.x;
    if (i < N) g_deg[i] = 0;
    if (i < 3) g_acc[i] = 0.0;
    if (i < RK * RK) g_gram[i] = 0.0;
}

// degree histogram from row indices (edge_index is int32)
__global__ void k_deg(const int* __restrict__ ei, int E) {
    int e = blockIdx.x * blockDim.x + threadIdx.x;
    if (e < E) atomicAdd(&g_deg[ei[e]], 1);
}

// ---------------------------------------------------------------------------
__device__ __forceinline__ unsigned f2_to_e4m3x2(float a, float b) {
    return (unsigned)__nv_cvt_float2_to_fp8x2(make_float2(a, b),
                                              __NV_SATFINITE, __NV_E4M3);
}

// Pack per-node scaled rows to fp8 (48B); fuse dinv + sum(z_mean^2).
// 8 threads per node row; 256 threads -> 32 rows/block.
__global__ void __launch_bounds__(256) k_pack(
    const float* __restrict__ zm, const float* __restrict__ zs, int N) {
    const float MS = 0.17677669529663687f;  // 1/sqrt(32)
    int sub = threadIdx.x & 7;
    int row = blockIdx.x * 32 + (threadIdx.x >> 3);

    float acc = 0.0f;
    if (row < N) {
        int d = g_deg[row];
        float di = (d > 0) ? rsqrtf((float)d) : 0.0f;
        if (sub == 0) g_dinv[row] = di;
        float ms = di * MS;
        // mean: 8 lanes x float4 = full 32-float row -> 4 fp8 each
        float4 mv = ((const float4*)(zm + (size_t)row * DM))[sub];
        acc = mv.x * mv.x + mv.y * mv.y + mv.z * mv.z + mv.w * mv.w;
        unsigned lo = f2_to_e4m3x2(mv.x * ms, mv.y * ms);
        unsigned hi = f2_to_e4m3x2(mv.z * ms, mv.w * ms);
        g_pack[(size_t)row * PKW32 + sub] = lo | (hi << 16);
        // std: lanes 0-3 x float4 = 16-float row
        if (sub < 4) {
            float4 sv = ((const float4*)(zs + (size_t)row * RK))[sub];
            unsigned slo = f2_to_e4m3x2(sv.x * di, sv.y * di);
            unsigned shi = f2_to_e4m3x2(sv.z * di, sv.w * di);
            g_pack[(size_t)row * PKW32 + 8 + sub] = slo | (shi << 16);
        }
    }
    // block reduce sumsq
    for (int o = 16; o; o >>= 1) acc += __shfl_xor_sync(0xffffffffu, acc, o);
    __shared__ float sh[8];
    int w = threadIdx.x >> 5, l = threadIdx.x & 31;
    if (l == 0) sh[w] = acc;
    __syncthreads();
    if (threadIdx.x == 0) {
        float s = 0.0f;
        for (int i = 0; i < 8; i++) s += sh[i];
        atomicAdd(&g_acc[0], (double)s);
    }
}

// Gram = z_std^T z_std via 256-row shared tiles
__global__ void k_gram(const float* __restrict__ zs, int N) {
    __shared__ float sh[256 * RK];
    int row0 = blockIdx.x * 256;
    for (int t = threadIdx.x; t < 256 * RK / 4; t += blockDim.x) {
        int row = row0 + (t >> 2);
        float4 v = make_float4(0.f, 0.f, 0.f, 0.f);
        if (row < N) v = ((const float4*)zs)[(size_t)row0 * 4 + t];
        ((float4*)sh)[t] = v;
    }
    __syncthreads();
    int a = threadIdx.x >> 4, b = threadIdx.x & 15;
    float acc = 0.0f;
#pragma unroll 8
    for (int i = 0; i < 256; i++) acc += sh[i * RK + a] * sh[i * RK + b];
    atomicAdd(&g_gram[threadIdx.x], (double)acc);
}

// ---------------------------------------------------------------------------
__device__ __forceinline__ __half2 cvt_e4m3x2(unsigned v) {
    __half2_raw hr = __nv_cvt_fp8x2_to_halfraw2((__nv_fp8x2_storage_t)(unsigned short)v,
                                                __NV_E4M3);
    __half2 h;
    *(__half2_raw*)&h = hr;
    return h;
}

// dot of 16 e4m3 pairs held in two uint4
__device__ __forceinline__ float dot16(uint4 a, uint4 b) {
    unsigned aw[4] = {a.x, a.y, a.z, a.w};
    unsigned bw[4] = {b.x, b.y, b.z, b.w};
    __half2 h = __float2half2_rn(0.f);
#pragma unroll
    for (int k = 0; k < 4; k++) {
        h = __hfma2(cvt_e4m3x2(aw[k]), cvt_e4m3x2(bw[k]), h);
        h = __hfma2(cvt_e4m3x2(aw[k] >> 16), cvt_e4m3x2(bw[k] >> 16), h);
    }
    float2 f = __half22float2(h);
    return f.x + f.y;
}

// Dominant kernel: per-edge fused dot of packed fp8 rows.
// 4 threads/edge: lanes 0-2 load 16B chunks, lane 3 handles rare self-loops.
// No per-edge reductions: lanes accumulate privately, one reduce at end.
__global__ void __launch_bounds__(256) k_edges(const int* __restrict__ ei, int E) {
    int tid = blockIdx.x * blockDim.x + threadIdx.x;
    int sub = threadIdx.x & 3;
    int gid = tid >> 2;
    int gstride = (gridDim.x * blockDim.x) >> 2;

    float accD = 0.0f, aself = 0.0f;

    int iters = (E + gstride - 1) / gstride;
    // main iterations: e < E guaranteed (gstride*(iters-1) < E)
    for (int it = 0; it < iters - 1; it++) {
        int e = gid + it * gstride;
        int r = ei[e];
        int c = ei[(size_t)E + e];
        if (sub < 3) {
            uint4 ua = ((const uint4*)(g_pack + (size_t)r * PKW32))[sub];
            uint4 ub = ((const uint4*)(g_pack + (size_t)c * PKW32))[sub];
            accD += dot16(ua, ub);
        } else if (r == c) {
            float di = g_dinv[r];
            aself += di * di;
        }
    }
    // guarded tail
    {
        int e = gid + (iters - 1) * gstride;
        if (e < E) {
            int r = ei[e];
            int c = ei[(size_t)E + e];
            if (sub < 3) {
                uint4 ua = ((const uint4*)(g_pack + (size_t)r * PKW32))[sub];
                uint4 ub = ((const uint4*)(g_pack + (size_t)c * PKW32))[sub];
                accD += dot16(ua, ub);
            } else if (r == c) {
                float di = g_dinv[r];
                aself += di * di;
            }
        }
    }

    // block reduce
    for (int o = 16; o; o >>= 1) {
        accD += __shfl_xor_sync(0xffffffffu, accD, o);
        aself += __shfl_xor_sync(0xffffffffu, aself, o);
    }
    __shared__ float s0[8], s1[8];
    int w = threadIdx.x >> 5, l = threadIdx.x & 31;
    if (l == 0) { s0[w] = accD; s1[w] = aself; }
    __syncthreads();
    if (threadIdx.x == 0) {
        float A = 0.f, B = 0.f;
        for (int i = 0; i < 8; i++) { A += s0[i]; B += s1[i]; }
        atomicAdd(&g_acc[1], (double)A);
        atomicAdd(&g_acc[2], (double)B);
    }
}

// finalize: logdet(I + Gram) via double Cholesky, combine, write scalar
__global__ void k_final(float* out, int N) {
    if (threadIdx.x == 0 && blockIdx.x == 0) {
        double M[RK][RK];
        double tr = 0.0;
        for (int i = 0; i < RK; i++) {
            for (int j = 0; j < RK; j++)
                M[i][j] = g_gram[i * RK + j] + (i == j ? 1.0 : 0.0);
            tr += g_gram[i * RK + i];  // sum(z_std^2) = trace(Gram)
        }
        double logdet = 0.0;
        for (int k = 0; k < RK; k++) {
            double d = M[k][k];
            for (int j = 0; j < k; j++) d -= M[k][j] * M[k][j];
            double lkk = sqrt(d);
            logdet += log(lkk);
            M[k][k] = lkk;
            for (int i = k + 1; i < RK; i++) {
                double s = M[i][k];
                for (int j = 0; j < k; j++) s -= M[i][j] * M[k][j];
                M[i][k] = s / lkk;
            }
        }
        logdet *= 2.0;

        double trace_L = (double)N - g_acc[2];
        // loss = (sumsq_m/32 + tr + trace_L - D - logdet) / (2N)
        double res = (g_acc[0] / (double)DM + tr + trace_L - g_acc[1] - logdet)
                     / (2.0 * (double)N);
        out[0] = (float)res;
    }
}

// ---------------------------------------------------------------------------
extern "C" void kernel_launch(void* const* d_in, const int* in_sizes, int n_in,
                              void* d_out, int out_size) {
    const float* zm = (const float*)d_in[0];
    const float* zs = (const float*)d_in[1];
    const int*   ei = (const int*)d_in[2];

    int N = in_sizes[0] / DM;
    int E = in_sizes[2] / 2;

    int nb = (N + 255) / 256;
    k_zero<<<nb, 256>>>(N);
    k_deg<<<(E + 255) / 256, 256>>>(ei, E);
    k_pack<<<(N + 31) / 32, 256>>>(zm, zs, N);
    k_gram<<<nb, 256>>>(zs, N);
    k_edges<<<1184, 256>>>(ei, E);   // one full wave @ 2048 thr/SM
    k_final<<<1, 32>>>((float*)d_out, N);
}